// round 2
// baseline (speedup 1.0000x reference)
#include <cuda_runtime.h>

// MeshfreeKANNet: u[m] = (sum_n phi_win[m,n]*w[n]) / (sum_n phi_win[m,n] + 1e-10)
// phi_win nonzero only for dist(x_m, node_n) <= RADIUS (cubic window support).
// Strategy: warp per point m; phase-1 ballot-compaction of in-radius node
// indices into smem, phase-2 dense KAN eval over compacted hits only.

#define MM      4096
#define NN      1024
#define HIDN    8
#define WARPS   8          // warps per block
#define THREADS 256
#define BLOCKS  (MM / WARPS)

#define RADIUS_F 0.3f
#define R2_F     0.09f
#define INV_R    (1.0f / 0.3f)
#define INV_H    (1.0f / 0.75f)

__global__ __launch_bounds__(THREADS)
void meshfree_kan_kernel(const float* __restrict__ x,
                         const float* __restrict__ nodes,
                         const float* __restrict__ W1a,
                         const float* __restrict__ W1b,
                         const float* __restrict__ W2,
                         const float* __restrict__ w,
                         float* __restrict__ out)
{
    __shared__ float s_nx[NN];
    __shared__ float s_ny[NN];
    __shared__ float s_w[NN];
    __shared__ float s_W1a[HIDN * 5];
    __shared__ float s_W1b[HIDN * 5];
    __shared__ float s_W2 [HIDN * 5];
    __shared__ int   s_buf[WARPS][NN];   // compacted hit indices per warp

    const int tid = threadIdx.x;

    // Cooperative load of all small operands into shared (SoA nodes).
    for (int i = tid; i < NN; i += THREADS) {
        s_nx[i] = nodes[2 * i];
        s_ny[i] = nodes[2 * i + 1];
        s_w[i]  = w[i];
    }
    if (tid < HIDN * 5) {
        s_W1a[tid] = W1a[tid];
        s_W1b[tid] = W1b[tid];
        s_W2[tid]  = W2[tid];
    }
    __syncthreads();

    const int warp = tid >> 5;
    const int lane = tid & 31;
    const int m = blockIdx.x * WARPS + warp;

    const float px = x[2 * m];
    const float py = x[2 * m + 1];

    const float grid0 = -1.5f, grid1 = -0.75f, grid2 = 0.0f,
                grid3 =  0.75f, grid4 = 1.5f;
    const float gridv[5] = {grid0, grid1, grid2, grid3, grid4};

    // ---- Phase 1: distance filter + warp stream compaction ----
    int cnt = 0;
    const unsigned lmask = (1u << lane) - 1u;
    #pragma unroll 4
    for (int base = 0; base < NN; base += 32) {
        const int n = base + lane;
        const float dx = px - s_nx[n];
        const float dy = py - s_ny[n];
        const float d2 = fmaf(dx, dx, dy * dy);
        const bool hit = (d2 <= R2_F);
        const unsigned msk = __ballot_sync(0xffffffffu, hit);
        if (hit) s_buf[warp][cnt + __popc(msk & lmask)] = n;
        cnt += __popc(msk);
    }
    __syncwarp();

    // ---- Phase 2: KAN evaluation over compacted in-radius nodes ----
    float S = 0.0f, Sw = 0.0f;
    for (int i = lane; i < cnt; i += 32) {
        const int n = s_buf[warp][i];
        const float dx = px - s_nx[n];
        const float dy = py - s_ny[n];
        const float d2 = fmaf(dx, dx, dy * dy);
        const float kx = dx * INV_R;
        const float ky = dy * INV_R;

        // hat basis of the two KAN inputs (5 each)
        float ba[5], bb[5];
        #pragma unroll
        for (int s = 0; s < 5; s++) {
            ba[s] = fmaxf(0.0f, 1.0f - fabsf(kx - gridv[s]) * INV_H);
            bb[s] = fmaxf(0.0f, 1.0f - fabsf(ky - gridv[s]) * INV_H);
        }

        // layer 1 (HID=8 tiny GEMM) + layer 2 (hat basis of hidden · W2)
        float phi_raw = 0.0f;
        #pragma unroll
        for (int h = 0; h < HIDN; h++) {
            float hv = 0.0f;
            #pragma unroll
            for (int s = 0; s < 5; s++) {
                hv = fmaf(ba[s], s_W1a[h * 5 + s], hv);
                hv = fmaf(bb[s], s_W1b[h * 5 + s], hv);
            }
            #pragma unroll
            for (int s = 0; s < 5; s++) {
                const float bh = fmaxf(0.0f, 1.0f - fabsf(hv - gridv[s]) * INV_H);
                phi_raw = fmaf(bh, s_W2[h * 5 + s], phi_raw);
            }
        }

        // cubic window: 1 - 6q^2 + 8q^3 - 3q^4
        const float q = sqrtf(d2) * INV_R;
        const float win = fmaf(q * q, fmaf(fmaf(-3.0f, q, 8.0f), q, -6.0f), 1.0f);

        const float phi = phi_raw * win;
        S  += phi;
        Sw  = fmaf(phi, s_w[n], Sw);
    }

    // ---- Warp reduction + normalize ----
    #pragma unroll
    for (int o = 16; o > 0; o >>= 1) {
        S  += __shfl_xor_sync(0xffffffffu, S,  o);
        Sw += __shfl_xor_sync(0xffffffffu, Sw, o);
    }
    if (lane == 0) out[m] = Sw / (S + 1e-10f);
}

extern "C" void kernel_launch(void* const* d_in, const int* in_sizes, int n_in,
                              void* d_out, int out_size)
{
    const float* x     = (const float*)d_in[0];   // [4096, 2]
    const float* nodes = (const float*)d_in[1];   // [1024, 2]
    const float* W1a   = (const float*)d_in[2];   // [8, 5]
    const float* W1b   = (const float*)d_in[3];   // [8, 5]
    const float* W2    = (const float*)d_in[4];   // [1, 40]
    const float* w     = (const float*)d_in[5];   // [1024, 1]
    float* out = (float*)d_out;                   // [4096, 1]

    meshfree_kan_kernel<<<BLOCKS, THREADS>>>(x, nodes, W1a, W1b, W2, w, out);
}

// round 4
// speedup vs baseline: 1.3704x; 1.3704x over previous
#include <cuda_runtime.h>

// MeshfreeKANNet: u[m] = (sum_n phi_win[m,n]*w[n]) / (sum_n phi_win[m,n] + 1e-10)
// phi_win nonzero only for dist <= RADIUS=0.3 (~7% of the 4096x1024 pairs).
// Warp per point: ballot-compaction of in-radius nodes, then dense KAN eval
// (math kept bit-faithful to the reference hat/window formulation; the
// sparse-hat algebraic shortcut pushed rel_err over 1e-3 in R3).
// Perf levers vs R2: 64-reg cap -> 4 blocks/SM -> single wave (592 slots for
// 512 blocks), u16 hit buffer, partial unroll to avoid deep-pipeline spills.

#define MM      4096
#define NN      1024
#define HIDN    8
#define WARPS   8
#define THREADS 256
#define BLOCKS  (MM / WARPS)

#define R2_F     0.09f
#define INV_R    (1.0f / 0.3f)
#define INV_H    (1.0f / 0.75f)

__global__ __launch_bounds__(THREADS, 4)
void meshfree_kan_kernel(const float* __restrict__ x,
                         const float* __restrict__ nodes,
                         const float* __restrict__ W1a,
                         const float* __restrict__ W1b,
                         const float* __restrict__ W2,
                         const float* __restrict__ w,
                         float* __restrict__ out)
{
    __shared__ float s_nx[NN];
    __shared__ float s_ny[NN];
    __shared__ float s_w[NN];
    __shared__ float s_W1a[HIDN * 5];
    __shared__ float s_W1b[HIDN * 5];
    __shared__ float s_W2 [HIDN * 5];
    __shared__ unsigned short s_buf[WARPS][NN];  // compacted hit indices

    const int tid = threadIdx.x;

    for (int i = tid; i < NN; i += THREADS) {
        s_nx[i] = nodes[2 * i];
        s_ny[i] = nodes[2 * i + 1];
        s_w[i]  = w[i];
    }
    if (tid < HIDN * 5) {
        s_W1a[tid] = W1a[tid];
        s_W1b[tid] = W1b[tid];
        s_W2[tid]  = W2[tid];
    }
    __syncthreads();

    const int warp = tid >> 5;
    const int lane = tid & 31;
    const int m = blockIdx.x * WARPS + warp;

    const float px = x[2 * m];
    const float py = x[2 * m + 1];

    const float gridv[5] = {-1.5f, -0.75f, 0.0f, 0.75f, 1.5f};

    // ---- Phase 1: distance filter + warp stream compaction ----
    int cnt = 0;
    const unsigned lmask = (1u << lane) - 1u;
    #pragma unroll 4
    for (int base = 0; base < NN; base += 32) {
        const int n = base + lane;
        const float dx = px - s_nx[n];
        const float dy = py - s_ny[n];
        const float d2 = fmaf(dx, dx, dy * dy);
        const bool hit = (d2 <= R2_F);
        const unsigned msk = __ballot_sync(0xffffffffu, hit);
        if (hit) s_buf[warp][cnt + __popc(msk & lmask)] = (unsigned short)n;
        cnt += __popc(msk);
    }
    __syncwarp();

    // ---- Phase 2: dense KAN evaluation over compacted nodes ----
    float S = 0.0f, Sw = 0.0f;
    for (int i = lane; i < cnt; i += 32) {
        const int n = (int)s_buf[warp][i];
        const float dx = px - s_nx[n];
        const float dy = py - s_ny[n];
        const float d2 = fmaf(dx, dx, dy * dy);
        const float kx = dx * INV_R;
        const float ky = dy * INV_R;

        // hat basis of the two KAN inputs (5 each), reference formulation
        float ba[5], bb[5];
        #pragma unroll
        for (int s = 0; s < 5; s++) {
            ba[s] = fmaxf(0.0f, 1.0f - fabsf(kx - gridv[s]) * INV_H);
            bb[s] = fmaxf(0.0f, 1.0f - fabsf(ky - gridv[s]) * INV_H);
        }

        // layer 1 (HID=8 tiny GEMM) + layer 2 (hat basis of hidden . W2)
        float phi_raw = 0.0f;
        #pragma unroll 2
        for (int h = 0; h < HIDN; h++) {
            float hv = 0.0f;
            #pragma unroll
            for (int s = 0; s < 5; s++) {
                hv = fmaf(ba[s], s_W1a[h * 5 + s], hv);
                hv = fmaf(bb[s], s_W1b[h * 5 + s], hv);
            }
            #pragma unroll
            for (int s = 0; s < 5; s++) {
                const float bh = fmaxf(0.0f, 1.0f - fabsf(hv - gridv[s]) * INV_H);
                phi_raw = fmaf(bh, s_W2[h * 5 + s], phi_raw);
            }
        }

        // cubic window: 1 - 6q^2 + 8q^3 - 3q^4
        const float q = sqrtf(d2) * INV_R;
        const float win = fmaf(q * q, fmaf(fmaf(-3.0f, q, 8.0f), q, -6.0f), 1.0f);

        const float phi = phi_raw * win;
        S  += phi;
        Sw  = fmaf(phi, s_w[n], Sw);
    }

    // ---- Warp reduction + normalize ----
    #pragma unroll
    for (int o = 16; o > 0; o >>= 1) {
        S  += __shfl_xor_sync(0xffffffffu, S,  o);
        Sw += __shfl_xor_sync(0xffffffffu, Sw, o);
    }
    if (lane == 0) out[m] = Sw / (S + 1e-10f);
}

extern "C" void kernel_launch(void* const* d_in, const int* in_sizes, int n_in,
                              void* d_out, int out_size)
{
    const float* x     = (const float*)d_in[0];   // [4096, 2]
    const float* nodes = (const float*)d_in[1];   // [1024, 2]
    const float* W1a   = (const float*)d_in[2];   // [8, 5]
    const float* W1b   = (const float*)d_in[3];   // [8, 5]
    const float* W2    = (const float*)d_in[4];   // [1, 40]
    const float* w     = (const float*)d_in[5];   // [1024, 1]
    float* out = (float*)d_out;                   // [4096, 1]

    meshfree_kan_kernel<<<BLOCKS, THREADS>>>(x, nodes, W1a, W1b, W2, w, out);
}

// round 6
// speedup vs baseline: 1.5383x; 1.1225x over previous
#include <cuda_runtime.h>

// MeshfreeKANNet: u[m] = (sum_n phi_win[m,n]*w[n]) / (sum_n phi_win[m,n] + 1e-10)
// Warp per point: ballot-compaction of in-radius (~7%) nodes, dense KAN eval.
// R5: weights for each hidden unit packed into one 16-float smem line so the
// inner loop issues 4 broadcast LDS.128 per h instead of 15 scalar LDS
// (120 -> 32 LDS per hit). FMA chain order kept bit-identical to R4 (the
// normalization denominator amplifies ~1e-7 perturbations ~10x; R3 lesson).

#define MM      4096
#define NN      1024
#define HIDN    8
#define WARPS   8
#define THREADS 256
#define BLOCKS  (MM / WARPS)

#define R2_F     0.09f
#define INV_R    (1.0f / 0.3f)
#define INV_H    (1.0f / 0.75f)

__global__ __launch_bounds__(THREADS, 4)
void meshfree_kan_kernel(const float* __restrict__ x,
                         const float* __restrict__ nodes,
                         const float* __restrict__ W1a,
                         const float* __restrict__ W1b,
                         const float* __restrict__ W2,
                         const float* __restrict__ w,
                         float* __restrict__ out)
{
    __shared__ float s_nx[NN];
    __shared__ float s_ny[NN];
    __shared__ float s_w[NN];
    // Packed weights: s_Wp[h] = {W1a[h][0..4], W1b[h][0..4], W2[h][0..4], 0}
    __shared__ float4 s_Wp[HIDN][4];
    __shared__ unsigned short s_buf[WARPS][NN];  // compacted hit indices

    const int tid = threadIdx.x;

    for (int i = tid; i < NN; i += THREADS) {
        s_nx[i] = nodes[2 * i];
        s_ny[i] = nodes[2 * i + 1];
        s_w[i]  = w[i];
    }
    if (tid < HIDN * 16) {
        const int h = tid >> 4;
        const int e = tid & 15;
        float v = 0.0f;
        if (e < 5)       v = W1a[h * 5 + e];
        else if (e < 10) v = W1b[h * 5 + (e - 5)];
        else if (e < 15) v = W2 [h * 5 + (e - 10)];
        ((float*)s_Wp)[tid] = v;
    }
    __syncthreads();

    const int warp = tid >> 5;
    const int lane = tid & 31;
    const int m = blockIdx.x * WARPS + warp;

    const float px = x[2 * m];
    const float py = x[2 * m + 1];

    const float gridv[5] = {-1.5f, -0.75f, 0.0f, 0.75f, 1.5f};

    // ---- Phase 1: distance filter + warp stream compaction ----
    int cnt = 0;
    const unsigned lmask = (1u << lane) - 1u;
    #pragma unroll 4
    for (int base = 0; base < NN; base += 32) {
        const int n = base + lane;
        const float dx = px - s_nx[n];
        const float dy = py - s_ny[n];
        const float d2 = fmaf(dx, dx, dy * dy);
        const bool hit = (d2 <= R2_F);
        const unsigned msk = __ballot_sync(0xffffffffu, hit);
        if (hit) s_buf[warp][cnt + __popc(msk & lmask)] = (unsigned short)n;
        cnt += __popc(msk);
    }
    __syncwarp();

    // ---- Phase 2: dense KAN evaluation over compacted nodes ----
    float S = 0.0f, Sw = 0.0f;
    for (int i = lane; i < cnt; i += 32) {
        const int n = (int)s_buf[warp][i];
        const float dx = px - s_nx[n];
        const float dy = py - s_ny[n];
        const float d2 = fmaf(dx, dx, dy * dy);
        const float kx = dx * INV_R;
        const float ky = dy * INV_R;

        // hat basis of the two KAN inputs (reference formulation, bit-exact)
        float ba[5], bb[5];
        #pragma unroll
        for (int s = 0; s < 5; s++) {
            ba[s] = fmaxf(0.0f, 1.0f - fabsf(kx - gridv[s]) * INV_H);
            bb[s] = fmaxf(0.0f, 1.0f - fabsf(ky - gridv[s]) * INV_H);
        }

        float phi_raw = 0.0f;
        #pragma unroll 2
        for (int h = 0; h < HIDN; h++) {
            const float4 q0 = s_Wp[h][0];
            const float4 q1 = s_Wp[h][1];
            const float4 q2 = s_Wp[h][2];
            const float4 q3 = s_Wp[h][3];
            const float wa[5]  = {q0.x, q0.y, q0.z, q0.w, q1.x};
            const float wb[5]  = {q1.y, q1.z, q1.w, q2.x, q2.y};
            const float w2r[5] = {q2.z, q2.w, q3.x, q3.y, q3.z};

            // layer 1: same interleaved FMA chain order as R4 (bit-exact)
            float hv = 0.0f;
            #pragma unroll
            for (int s = 0; s < 5; s++) {
                hv = fmaf(ba[s], wa[s], hv);
                hv = fmaf(bb[s], wb[s], hv);
            }
            // layer 2: hat basis of hidden value . W2 row
            #pragma unroll
            for (int s = 0; s < 5; s++) {
                const float bh = fmaxf(0.0f, 1.0f - fabsf(hv - gridv[s]) * INV_H);
                phi_raw = fmaf(bh, w2r[s], phi_raw);
            }
        }

        // cubic window: 1 - 6q^2 + 8q^3 - 3q^4
        const float q = sqrtf(d2) * INV_R;
        const float win = fmaf(q * q, fmaf(fmaf(-3.0f, q, 8.0f), q, -6.0f), 1.0f);

        const float phi = phi_raw * win;
        S  += phi;
        Sw  = fmaf(phi, s_w[n], Sw);
    }

    // ---- Warp reduction + normalize ----
    #pragma unroll
    for (int o = 16; o > 0; o >>= 1) {
        S  += __shfl_xor_sync(0xffffffffu, S,  o);
        Sw += __shfl_xor_sync(0xffffffffu, Sw, o);
    }
    if (lane == 0) out[m] = Sw / (S + 1e-10f);
}

extern "C" void kernel_launch(void* const* d_in, const int* in_sizes, int n_in,
                              void* d_out, int out_size)
{
    const float* x     = (const float*)d_in[0];   // [4096, 2]
    const float* nodes = (const float*)d_in[1];   // [1024, 2]
    const float* W1a   = (const float*)d_in[2];   // [8, 5]
    const float* W1b   = (const float*)d_in[3];   // [8, 5]
    const float* W2    = (const float*)d_in[4];   // [1, 40]
    const float* w     = (const float*)d_in[5];   // [1024, 1]
    float* out = (float*)d_out;                   // [4096, 1]

    meshfree_kan_kernel<<<BLOCKS, THREADS>>>(x, nodes, W1a, W1b, W2, w, out);
}